// round 12
// baseline (speedup 1.0000x reference)
#include <cuda_runtime.h>
#include <math.h>
#include <stdint.h>

// Problem constants
#define Bz   8
#define SQv  1024
#define SKv  1024
#define Dm   512
#define Hh   8
#define HDv  64
#define DFFv 2048
#define Mrows 8192   // B*SQ == B*SK

// Dense GEMM tiling
#define BM 128
#define BN 128
#define BK 16
#define ASTRIDE (BK + 4)           // 20 words: LDS conflict-free
#define WSTRIDE (BN + 8)           // 136 words: LDS conflict-free
#define ASZ (BM * ASTRIDE)         // 2560 words
#define WSZ (BK * WSTRIDE)         // 2176 words
#define SLOT (ASZ + WSZ)           // 4736 words per pipeline stage
#define GEMM_SMEM (4 * SLOT * 4)   // 75776 bytes (4 stages)

// attn smem layout (words): K0,V0 (32x72 each) | UB (128x72, later K1|V1|Ps)
#define KVW  (32 * 72)             // 2304 words
#define AUB  (2 * KVW)             // UB offset
#define UBW  (128 * 72)            // 9216 words
#define APS  (AUB + 2 * KVW)       // Ps offset (second half of UB)
#define ATTN_SMEM ((2 * KVW + UBW) * 4)   // 55296 bytes

// ---------------- scratch (static device memory; no runtime allocation) ----------------
__device__ float g_QH[4194304];     // [8192,512]
__device__ float g_KH[4194304];
__device__ float g_VH[4194304];
__device__ float g_ATT[4194304];
__device__ float g_F1[16777216];    // [8192,2048]
__device__ float g_S0[67108864];    // layer-0 pre-softmax scores [B,H,SQ,SK]

// ---------------- mma / cp.async helpers ----------------------------------------------
// mma consumes RAW fp32 bit patterns as tf32 (HW truncates low mantissa bits).
__device__ __forceinline__ void mma_tf32(float c[4], const unsigned a[4], const unsigned b[2]) {
    asm volatile(
        "mma.sync.aligned.m16n8k8.row.col.f32.tf32.tf32.f32 "
        "{%0,%1,%2,%3}, {%4,%5,%6,%7}, {%8,%9}, {%0,%1,%2,%3};\n"
        : "+f"(c[0]), "+f"(c[1]), "+f"(c[2]), "+f"(c[3])
        : "r"(a[0]), "r"(a[1]), "r"(a[2]), "r"(a[3]), "r"(b[0]), "r"(b[1]));
}

__device__ __forceinline__ void cp16(void* smem, const void* gmem) {
    unsigned saddr = (unsigned)__cvta_generic_to_shared(smem);
    asm volatile("cp.async.cg.shared.global [%0], [%1], 16;\n" :: "r"(saddr), "l"(gmem));
}

// ---------------- block reductions (blockDim.x == 256 assumed) ----------------
__device__ __forceinline__ float blk_sum256(float v) {
    __shared__ float s[8];
    int tid = threadIdx.x;
    #pragma unroll
    for (int o = 16; o > 0; o >>= 1) v += __shfl_xor_sync(0xffffffffu, v, o);
    __syncthreads();
    if ((tid & 31) == 0) s[tid >> 5] = v;
    __syncthreads();
    float r = 0.f;
    #pragma unroll
    for (int i = 0; i < 8; i++) r += s[i];
    return r;
}

// ---------------- dense GEMM (tf32): C = A[M,K] @ W[K,N] + bias (+GELU) ----------------
// CTA 128x128, 256 threads = 8 warps (4m x 2n), warp tile 32x64, BK=16.
// 4-slot / 3-outstanding cp.async pipeline, ONE __syncthreads per K-step.
// 16 warps/SM (2 CTAs) for latency hiding.
template<int ACT>
__global__ __launch_bounds__(256, 2)
void gemm_tf32(const float* __restrict__ A, const float* __restrict__ W,
               const float* __restrict__ bias, float* __restrict__ C,
               int M, int N, int K)
{
    extern __shared__ unsigned dynsm[];

    const int tid  = threadIdx.x;
    const int lane = tid & 31, warp = tid >> 5;
    const int wm = (warp >> 1) * 32;     // 0,32,64,96
    const int wn = (warp & 1) * 64;      // 0,64
    const int g = lane >> 2, tg = lane & 3;
    const int bm = blockIdx.y * BM, bn = blockIdx.x * BN;

    float acc[2][8][4];
    #pragma unroll
    for (int i = 0; i < 2; i++)
        #pragma unroll
        for (int j = 0; j < 8; j++)
            #pragma unroll
            for (int r = 0; r < 4; r++) acc[i][j][r] = 0.f;

    auto issue_tile = [&](int t, int st) {
        int kt = t * BK;
        unsigned* Ad = dynsm + st * SLOT;
        unsigned* Wd = Ad + ASZ;
        #pragma unroll
        for (int i = 0; i < 2; i++) {
            int f = tid + i * 256;
            cp16(&Ad[(f >> 2) * ASTRIDE + (f & 3) * 4],
                 &A[(size_t)(bm + (f >> 2)) * K + kt + (f & 3) * 4]);
        }
        #pragma unroll
        for (int i = 0; i < 2; i++) {
            int f = tid + i * 256;
            cp16(&Wd[(f >> 5) * WSTRIDE + (f & 31) * 4],
                 &W[(size_t)(kt + (f >> 5)) * N + bn + (f & 31) * 4]);
        }
        asm volatile("cp.async.commit_group;\n");
    };

    const int nt = K / BK;   // >= 32 always
    issue_tile(0, 0);
    issue_tile(1, 1);
    issue_tile(2, 2);

    for (int it = 0; it < nt; it++) {
        if (it + 2 < nt)      { asm volatile("cp.async.wait_group 2;\n"); }
        else if (it + 1 < nt) { asm volatile("cp.async.wait_group 1;\n"); }
        else                  { asm volatile("cp.async.wait_group 0;\n"); }
        __syncthreads();

        if (it + 3 < nt) issue_tile(it + 3, (it + 3) & 3);

        const unsigned* Asl = dynsm + (it & 3) * SLOT;
        const unsigned* Wsl = Asl + ASZ;

        #pragma unroll
        for (int ks = 0; ks < BK; ks += 8) {
            unsigned af[2][4], bf[8][2];
            #pragma unroll
            for (int mi = 0; mi < 2; mi++) {
                int r = wm + mi * 16 + g;
                af[mi][0] = Asl[r * ASTRIDE + ks + tg];
                af[mi][1] = Asl[(r + 8) * ASTRIDE + ks + tg];
                af[mi][2] = Asl[r * ASTRIDE + ks + tg + 4];
                af[mi][3] = Asl[(r + 8) * ASTRIDE + ks + tg + 4];
            }
            #pragma unroll
            for (int nj = 0; nj < 8; nj++) {
                int c = wn + nj * 8 + g;
                bf[nj][0] = Wsl[(ks + tg) * WSTRIDE + c];
                bf[nj][1] = Wsl[(ks + tg + 4) * WSTRIDE + c];
            }
            #pragma unroll
            for (int mi = 0; mi < 2; mi++)
                #pragma unroll
                for (int nj = 0; nj < 8; nj++)
                    mma_tf32(acc[mi][nj], af[mi], bf[nj]);
        }
    }

    #pragma unroll
    for (int mi = 0; mi < 2; mi++) {
        #pragma unroll
        for (int nj = 0; nj < 8; nj++) {
            int row = bm + wm + mi * 16 + g;
            int col = bn + wn + nj * 8 + tg * 2;
            float b0 = bias[col], b1 = bias[col + 1];
            float2 v0 = make_float2(acc[mi][nj][0] + b0, acc[mi][nj][1] + b1);
            float2 v1 = make_float2(acc[mi][nj][2] + b0, acc[mi][nj][3] + b1);
            if (ACT == 1) {
                v0.x = 0.5f * v0.x * (1.f + erff(v0.x * 0.7071067811865475f));
                v0.y = 0.5f * v0.y * (1.f + erff(v0.y * 0.7071067811865475f));
                v1.x = 0.5f * v1.x * (1.f + erff(v1.x * 0.7071067811865475f));
                v1.y = 0.5f * v1.y * (1.f + erff(v1.y * 0.7071067811865475f));
            }
            *(float2*)&C[(size_t)row * N + col]       = v0;
            *(float2*)&C[(size_t)(row + 8) * N + col] = v1;
        }
    }
}

// ---------------- fused attention: scores (+prev / +store S0) + online softmax + P@V ---
// CTA = 128 q-rows of one (b,h). 128 threads = 4 warps, each warp owns 32 q-rows
// (2 m-frags) -> K/V fragment LDS amortized over 2x mmas. K/V tiles (32x64) via
// cp.async double buffer; buffer 1 + P buffer overlay the retired Q staging tile.
// layer 0: writes raw scaled scores to outS. layer 1: reads prevS.
__global__ __launch_bounds__(128)
void attn_fused(const float* __restrict__ QH, const float* __restrict__ KH,
                const float* __restrict__ VH, const float* __restrict__ scale,
                const float* __restrict__ extra, int layer,
                const float* __restrict__ prevS, float* __restrict__ outS,
                float* __restrict__ O)
{
    extern __shared__ unsigned dynsm[];
    unsigned* K0 = dynsm;
    unsigned* V0 = dynsm + KVW;
    unsigned* UB = dynsm + AUB;          // Q staging (128x72)
    unsigned* K1 = UB;                   // after Q retire
    unsigned* V1 = UB + KVW;
    unsigned* PsAll = dynsm + APS;       // 4 warps x 32x36

    const int tid = threadIdx.x;
    const int lane = tid & 31, warp = tid >> 5;
    const int g = lane >> 2, tg = lane & 3;
    const int wq = warp * 32;
    const int bh = blockIdx.y, b = bh >> 3, h = bh & 7;
    const int q0 = blockIdx.x * 128;
    const float* Qb = QH + (size_t)b * SQv * Dm + h * HDv;
    const float* Kb = KH + (size_t)b * SKv * Dm + h * HDv;
    const float* Vb = VH + (size_t)b * SKv * Dm + h * HDv;
    unsigned* Psw = PsAll + warp * (32 * 36);

    auto issue_kv = [&](int t, unsigned* Kd, unsigned* Vd) {
        int kt = t * 32;
        #pragma unroll
        for (int i = 0; i < 4; i++) {
            int f = tid + i * 128;
            int r = f >> 4, c = (f & 15) * 4;
            cp16(&Kd[r * 72 + c], &Kb[(size_t)(kt + r) * Dm + c]);
            cp16(&Vd[r * 72 + c], &Vb[(size_t)(kt + r) * Dm + c]);
        }
        asm volatile("cp.async.commit_group;\n");
    };

    // group 0: K/V tile 0; group 1: Q tile (128x64) -> UB
    issue_kv(0, K0, V0);
    #pragma unroll
    for (int i = 0; i < 16; i++) {
        int f = tid + i * 128;
        int r = f >> 4, c = (f & 15) * 4;
        cp16(&UB[r * 72 + c], &Qb[(size_t)(q0 + r) * Dm + c]);
    }
    asm volatile("cp.async.commit_group;\n");
    asm volatile("cp.async.wait_group 0;\n");
    __syncthreads();

    // stage Q fragments: 8 kc x 2 mi x 4 regs = 64 regs
    unsigned qf[8][2][4];
    #pragma unroll
    for (int kc = 0; kc < 8; kc++)
        #pragma unroll
        for (int mi = 0; mi < 2; mi++) {
            int r = (wq + mi * 16 + g) * 72;
            qf[kc][mi][0] = UB[r + kc * 8 + tg];
            qf[kc][mi][1] = UB[r + 8 * 72 + kc * 8 + tg];
            qf[kc][mi][2] = UB[r + kc * 8 + tg + 4];
            qf[kc][mi][3] = UB[r + 8 * 72 + kc * 8 + tg + 4];
        }
    __syncthreads();   // UB retired -> becomes K1/V1/Ps
    issue_kv(1, K1, V1);

    float e = extra[layer];
    e = fminf(fmaxf(e, 0.01f), 50.0f);
    const float eff = scale[layer] * e;

    float m[2][2], l[2][2];
    #pragma unroll
    for (int mi = 0; mi < 2; mi++) { m[mi][0] = -INFINITY; m[mi][1] = -INFINITY; l[mi][0] = 0.f; l[mi][1] = 0.f; }
    float oacc[2][8][4];
    #pragma unroll
    for (int mi = 0; mi < 2; mi++)
        #pragma unroll
        for (int j = 0; j < 8; j++)
            #pragma unroll
            for (int r = 0; r < 4; r++) oacc[mi][j][r] = 0.f;

    size_t srowA[2], srowB[2];
    #pragma unroll
    for (int mi = 0; mi < 2; mi++) {
        int rowA = q0 + wq + mi * 16 + g;
        srowA[mi] = ((size_t)bh * SQv + rowA) * SKv;
        srowB[mi] = srowA[mi] + (size_t)8 * SKv;
    }

    for (int it = 0; it < 32; it++) {
        const int kt = it * 32;
        unsigned* Kc = (it & 1) ? K1 : K0;
        unsigned* Vc = (it & 1) ? V1 : V0;

        if (it < 31) { asm volatile("cp.async.wait_group 1;\n"); }
        else         { asm volatile("cp.async.wait_group 0;\n"); }
        __syncthreads();

        // ---- scores: s[mi][nj] = Q(32) x K^T(32), d = 64 ----
        float s[2][4][4];
        #pragma unroll
        for (int mi = 0; mi < 2; mi++)
            #pragma unroll
            for (int j = 0; j < 4; j++)
                #pragma unroll
                for (int r = 0; r < 4; r++) s[mi][j][r] = 0.f;
        #pragma unroll
        for (int kc = 0; kc < 8; kc++) {
            unsigned bf[4][2];
            #pragma unroll
            for (int nj = 0; nj < 4; nj++) {
                int c = (nj * 8 + g) * 72;
                bf[nj][0] = Kc[c + kc * 8 + tg];
                bf[nj][1] = Kc[c + kc * 8 + tg + 4];
            }
            #pragma unroll
            for (int mi = 0; mi < 2; mi++)
                #pragma unroll
                for (int nj = 0; nj < 4; nj++)
                    mma_tf32(s[mi][nj], qf[kc][mi], bf[nj]);
        }

        // ---- scale, add prev / store raw scores ----
        if (prevS) {
            #pragma unroll
            for (int mi = 0; mi < 2; mi++)
                #pragma unroll
                for (int nj = 0; nj < 4; nj++) {
                    int col = kt + nj * 8 + tg * 2;
                    float2 p0 = *(const float2*)&prevS[srowA[mi] + col];
                    float2 p8 = *(const float2*)&prevS[srowB[mi] + col];
                    s[mi][nj][0] = fmaf(s[mi][nj][0], eff, p0.x);
                    s[mi][nj][1] = fmaf(s[mi][nj][1], eff, p0.y);
                    s[mi][nj][2] = fmaf(s[mi][nj][2], eff, p8.x);
                    s[mi][nj][3] = fmaf(s[mi][nj][3], eff, p8.y);
                }
        } else {
            #pragma unroll
            for (int mi = 0; mi < 2; mi++)
                #pragma unroll
                for (int nj = 0; nj < 4; nj++) {
                    s[mi][nj][0] *= eff; s[mi][nj][1] *= eff;
                    s[mi][nj][2] *= eff; s[mi][nj][3] *= eff;
                    int col = kt + nj * 8 + tg * 2;
                    *(float2*)&outS[srowA[mi] + col] = make_float2(s[mi][nj][0], s[mi][nj][1]);
                    *(float2*)&outS[srowB[mi] + col] = make_float2(s[mi][nj][2], s[mi][nj][3]);
                }
        }

        // ---- online softmax update (per mi, per half) ----
        #pragma unroll
        for (int mi = 0; mi < 2; mi++) {
            float tmA = -INFINITY, tmB = -INFINITY;
            #pragma unroll
            for (int nj = 0; nj < 4; nj++) {
                tmA = fmaxf(tmA, fmaxf(s[mi][nj][0], s[mi][nj][1]));
                tmB = fmaxf(tmB, fmaxf(s[mi][nj][2], s[mi][nj][3]));
            }
            tmA = fmaxf(tmA, __shfl_xor_sync(0xffffffffu, tmA, 1));
            tmA = fmaxf(tmA, __shfl_xor_sync(0xffffffffu, tmA, 2));
            tmB = fmaxf(tmB, __shfl_xor_sync(0xffffffffu, tmB, 1));
            tmB = fmaxf(tmB, __shfl_xor_sync(0xffffffffu, tmB, 2));

            float nmA = fmaxf(m[mi][0], tmA), nmB = fmaxf(m[mi][1], tmB);
            float cA = __expf(m[mi][0] - nmA), cB = __expf(m[mi][1] - nmB);
            float rsA = 0.f, rsB = 0.f;
            #pragma unroll
            for (int nj = 0; nj < 4; nj++) {
                s[mi][nj][0] = __expf(s[mi][nj][0] - nmA);
                s[mi][nj][1] = __expf(s[mi][nj][1] - nmA);
                s[mi][nj][2] = __expf(s[mi][nj][2] - nmB);
                s[mi][nj][3] = __expf(s[mi][nj][3] - nmB);
                rsA += s[mi][nj][0] + s[mi][nj][1];
                rsB += s[mi][nj][2] + s[mi][nj][3];
            }
            rsA += __shfl_xor_sync(0xffffffffu, rsA, 1);
            rsA += __shfl_xor_sync(0xffffffffu, rsA, 2);
            rsB += __shfl_xor_sync(0xffffffffu, rsB, 1);
            rsB += __shfl_xor_sync(0xffffffffu, rsB, 2);
            l[mi][0] = l[mi][0] * cA + rsA;  l[mi][1] = l[mi][1] * cB + rsB;
            m[mi][0] = nmA;  m[mi][1] = nmB;
            #pragma unroll
            for (int nj = 0; nj < 8; nj++) {
                oacc[mi][nj][0] *= cA; oacc[mi][nj][1] *= cA;
                oacc[mi][nj][2] *= cB; oacc[mi][nj][3] *= cB;
            }
        }

        // ---- P: C-layout -> smem (stride 36, read-conflict-free) -> A-layout ----
        #pragma unroll
        for (int mi = 0; mi < 2; mi++)
            #pragma unroll
            for (int nj = 0; nj < 4; nj++) {
                Psw[(mi * 16 + g) * 36 + nj * 8 + tg * 2]     = __float_as_uint(s[mi][nj][0]);
                Psw[(mi * 16 + g) * 36 + nj * 8 + tg * 2 + 1] = __float_as_uint(s[mi][nj][1]);
                Psw[(mi * 16 + 8 + g) * 36 + nj * 8 + tg * 2]     = __float_as_uint(s[mi][nj][2]);
                Psw[(mi * 16 + 8 + g) * 36 + nj * 8 + tg * 2 + 1] = __float_as_uint(s[mi][nj][3]);
            }
        __syncwarp();
        unsigned pf[4][2][4];
        #pragma unroll
        for (int kc = 0; kc < 4; kc++)
            #pragma unroll
            for (int mi = 0; mi < 2; mi++) {
                int r = (mi * 16 + g) * 36;
                pf[kc][mi][0] = Psw[r + kc * 8 + tg];
                pf[kc][mi][1] = Psw[r + 8 * 36 + kc * 8 + tg];
                pf[kc][mi][2] = Psw[r + kc * 8 + tg + 4];
                pf[kc][mi][3] = Psw[r + 8 * 36 + kc * 8 + tg + 4];
            }

        // ---- O += P(32x32) @ V(32x64) ----
        #pragma unroll
        for (int kc = 0; kc < 4; kc++) {
            unsigned vb[8][2];
            #pragma unroll
            for (int nj = 0; nj < 8; nj++) {
                int c = nj * 8 + g;
                vb[nj][0] = Vc[(kc * 8 + tg) * 72 + c];
                vb[nj][1] = Vc[(kc * 8 + tg + 4) * 72 + c];
            }
            #pragma unroll
            for (int mi = 0; mi < 2; mi++)
                #pragma unroll
                for (int nj = 0; nj < 8; nj++)
                    mma_tf32(oacc[mi][nj], pf[kc][mi], vb[nj]);
        }

        __syncthreads();   // all warps done reading Kc/Vc
        if (it + 2 < 32) issue_kv(it + 2, Kc, Vc);   // refill the just-freed buffer
    }

    // ---- finalize: O /= l, write [b, q, h*64 + d] ----
    float* Ob = O + (size_t)b * SQv * Dm + h * HDv;
    #pragma unroll
    for (int mi = 0; mi < 2; mi++) {
        float iA = 1.f / l[mi][0], iB = 1.f / l[mi][1];
        int rowA = q0 + wq + mi * 16 + g;
        #pragma unroll
        for (int nj = 0; nj < 8; nj++) {
            int col = nj * 8 + tg * 2;
            *(float2*)&Ob[(size_t)rowA * Dm + col] =
                make_float2(oacc[mi][nj][0] * iA, oacc[mi][nj][1] * iA);
            *(float2*)&Ob[(size_t)(rowA + 8) * Dm + col] =
                make_float2(oacc[mi][nj][2] * iB, oacc[mi][nj][3] * iB);
        }
    }
}

// ---------------- gated residual + post-LayerNorm ----------------------
__global__ __launch_bounds__(256)
void addnorm_kernel(const float* __restrict__ qin, float* __restrict__ qout,
                    const float* __restrict__ delta,
                    const float* __restrict__ gate, const float* __restrict__ g,
                    const float* __restrict__ bb)
{
    const size_t row = blockIdx.x;
    const int tid = threadIdx.x;
    const float gt = gate[0];
    const float sp = (gt > 20.f) ? gt : log1pf(expf(gt));   // softplus

    float2 x = *(const float2*)&qin[row * Dm + tid * 2];
    float2 dd = *(const float2*)&delta[row * Dm + tid * 2];
    float y0 = x.x + sp * dd.x;
    float y1 = x.y + sp * dd.y;

    float s = blk_sum256(y0 + y1);
    float mu = s * (1.f / 512.f);
    float s2 = blk_sum256((y0 - mu) * (y0 - mu) + (y1 - mu) * (y1 - mu));
    float inv = rsqrtf(s2 * (1.f / 512.f) + 1e-5f);

    float2 o;
    o.x = (y0 - mu) * inv * g[tid * 2 + 0] + bb[tid * 2 + 0];
    o.y = (y1 - mu) * inv * g[tid * 2 + 1] + bb[tid * 2 + 1];
    *(float2*)&qout[row * Dm + tid * 2] = o;
}

// ---------------- launcher -------------------------------------------------------------
extern "C" void kernel_launch(void* const* d_in, const int* in_sizes, int n_in,
                              void* d_out, int out_size)
{
    (void)in_sizes; (void)n_in; (void)out_size;
    const float* q_in  = (const float*)d_in[0];
    const float* k_in  = (const float*)d_in[1];
    const float* v_in  = (const float*)d_in[2];
    const float* WQ    = (const float*)d_in[3];
    const float* bQ    = (const float*)d_in[4];
    const float* WK    = (const float*)d_in[5];
    const float* bK    = (const float*)d_in[6];
    const float* WV    = (const float*)d_in[7];
    const float* bV    = (const float*)d_in[8];
    const float* WO    = (const float*)d_in[9];
    const float* bO    = (const float*)d_in[10];
    const float* Wf1   = (const float*)d_in[11];
    const float* bf1   = (const float*)d_in[12];
    const float* Wf2   = (const float*)d_in[13];
    const float* bf2   = (const float*)d_in[14];
    const float* ln1g  = (const float*)d_in[15];
    const float* ln1b  = (const float*)d_in[16];
    const float* ln2g  = (const float*)d_in[17];
    const float* ln2b  = (const float*)d_in[18];
    const float* scale = (const float*)d_in[19];
    const float* extra = (const float*)d_in[20];
    const float* gA    = (const float*)d_in[21];
    const float* gF    = (const float*)d_in[22];

    float *QH, *KH, *VH, *ATT, *F1, *S0;
    cudaGetSymbolAddress((void**)&QH, g_QH);
    cudaGetSymbolAddress((void**)&KH, g_KH);
    cudaGetSymbolAddress((void**)&VH, g_VH);
    cudaGetSymbolAddress((void**)&ATT, g_ATT);
    cudaGetSymbolAddress((void**)&F1, g_F1);
    cudaGetSymbolAddress((void**)&S0, g_S0);

    // opt-in to >48KB dynamic smem (host state, capture-safe)
    cudaFuncSetAttribute(gemm_tf32<0>, cudaFuncAttributeMaxDynamicSharedMemorySize, GEMM_SMEM);
    cudaFuncSetAttribute(gemm_tf32<1>, cudaFuncAttributeMaxDynamicSharedMemorySize, GEMM_SMEM);
    cudaFuncSetAttribute(attn_fused,   cudaFuncAttributeMaxDynamicSharedMemorySize, ATTN_SMEM);

    float* qbuf = (float*)d_out;   // q lives in d_out after the first addnorm

    const dim3 gP(Dm / BN, Mrows / BM);        // (4, 64)  N=512 GEMMs
    const dim3 gF1(DFFv / BN, Mrows / BM);     // (16, 64) FFN1

    for (int i = 0; i < 2; i++) {
        const size_t wofD = (size_t)i * Dm * Dm;
        const size_t wofF = (size_t)i * Dm * DFFv;
        const float* qcur = (i == 0) ? q_in : qbuf;   // layer-0 reads the input directly

        gemm_tf32<0><<<gP, 256, GEMM_SMEM>>>(qcur, WQ + wofD, bQ + i * Dm, QH, Mrows, Dm, Dm);
        gemm_tf32<0><<<gP, 256, GEMM_SMEM>>>(k_in, WK + wofD, bK + i * Dm, KH, Mrows, Dm, Dm);
        gemm_tf32<0><<<gP, 256, GEMM_SMEM>>>(v_in, WV + wofD, bV + i * Dm, VH, Mrows, Dm, Dm);

        // fused scores(+prev/S0) + online softmax + P@V; attn-out overwrites QH
        const float* prev = (i == 0) ? nullptr : S0;
        float* Sout = (i == 0) ? S0 : nullptr;
        attn_fused<<<dim3(SQv / 128, Bz * Hh), 128, ATTN_SMEM>>>(QH, KH, VH, scale, extra, i,
                                                                 prev, Sout, QH);

        gemm_tf32<0><<<gP, 256, GEMM_SMEM>>>(QH, WO + wofD, bO + i * Dm, ATT, Mrows, Dm, Dm);
        addnorm_kernel<<<Mrows, 256>>>(qcur, qbuf, ATT, gA + i,
                                       ln1g + (size_t)i * Dm, ln1b + (size_t)i * Dm);

        gemm_tf32<1><<<gF1, 256, GEMM_SMEM>>>(qbuf, Wf1 + wofF, bf1 + i * DFFv, F1, Mrows, DFFv, Dm);
        gemm_tf32<0><<<gP, 256, GEMM_SMEM>>>(F1, Wf2 + wofF, bf2 + i * Dm, ATT, Mrows, Dm, DFFv);
        addnorm_kernel<<<Mrows, 256>>>(qbuf, qbuf, ATT, gF + i,
                                       ln2g + (size_t)i * Dm, ln2b + (size_t)i * Dm);
    }
}

// round 13
// speedup vs baseline: 1.0559x; 1.0559x over previous
#include <cuda_runtime.h>
#include <math.h>
#include <stdint.h>

// Problem constants
#define Bz   8
#define SQv  1024
#define SKv  1024
#define Dm   512
#define Hh   8
#define HDv  64
#define DFFv 2048
#define Mrows 8192   // B*SQ == B*SK

// Dense GEMM tiling
#define BM 128
#define BN 128
#define BK 16
#define ASTRIDE (BK + 4)           // 20 words: LDS conflict-free
#define WSTRIDE (BN + 8)           // 136 words: LDS conflict-free
#define ASZ (BM * ASTRIDE)         // 2560 words
#define WSZ (BK * WSTRIDE)         // 2176 words
#define SLOT (ASZ + WSZ)           // 4736 words per pipeline stage
#define GEMM_SMEM (4 * SLOT * 4)   // 75776 bytes (4 stages)

// attn smem layout (words): K0,V0 (32x72 each) | UB (128x72, later K1|V1|Ps)
#define KVW  (32 * 72)             // 2304 words
#define AUB  (2 * KVW)             // UB offset
#define UBW  (128 * 72)            // 9216 words
#define APS  (AUB + 2 * KVW)       // Ps offset (second half of UB)
#define ATTN_SMEM ((2 * KVW + UBW) * 4)   // 55296 bytes

// ---------------- scratch (static device memory; no runtime allocation) ----------------
__device__ float g_QH[4194304];     // [8192,512]
__device__ float g_KH[4194304];
__device__ float g_VH[4194304];
__device__ float g_ATT[4194304];
__device__ float g_F1[16777216];    // [8192,2048]
__device__ float g_S0[67108864];    // layer-0 pre-softmax scores [B,H,SQ,SK]

// ---------------- mma / cp.async helpers ----------------------------------------------
// mma consumes RAW fp32 bit patterns as tf32 (HW truncates low mantissa bits).
__device__ __forceinline__ void mma_tf32(float c[4], const unsigned a[4], const unsigned b[2]) {
    asm volatile(
        "mma.sync.aligned.m16n8k8.row.col.f32.tf32.tf32.f32 "
        "{%0,%1,%2,%3}, {%4,%5,%6,%7}, {%8,%9}, {%0,%1,%2,%3};\n"
        : "+f"(c[0]), "+f"(c[1]), "+f"(c[2]), "+f"(c[3])
        : "r"(a[0]), "r"(a[1]), "r"(a[2]), "r"(a[3]), "r"(b[0]), "r"(b[1]));
}

__device__ __forceinline__ void cp16(void* smem, const void* gmem) {
    unsigned saddr = (unsigned)__cvta_generic_to_shared(smem);
    asm volatile("cp.async.cg.shared.global [%0], [%1], 16;\n" :: "r"(saddr), "l"(gmem));
}

// ---------------- block reductions (blockDim.x == 256 assumed) ----------------
__device__ __forceinline__ float blk_sum256(float v) {
    __shared__ float s[8];
    int tid = threadIdx.x;
    #pragma unroll
    for (int o = 16; o > 0; o >>= 1) v += __shfl_xor_sync(0xffffffffu, v, o);
    __syncthreads();
    if ((tid & 31) == 0) s[tid >> 5] = v;
    __syncthreads();
    float r = 0.f;
    #pragma unroll
    for (int i = 0; i < 8; i++) r += s[i];
    return r;
}

// ---------------- dense GEMM (tf32): C = A[M,K] @ W[K,N] + bias (+GELU) ----------------
// CTA 128x128, 128 threads = 4 warps (2x2), warp tile 64x64, BK=16.
// 4-slot / 3-outstanding cp.async pipeline, ONE __syncthreads per K-step.
// (R11-verified configuration: ~154 TF/s)
template<int ACT>
__global__ __launch_bounds__(128)
void gemm_tf32(const float* __restrict__ A, const float* __restrict__ W,
               const float* __restrict__ bias, float* __restrict__ C,
               int M, int N, int K)
{
    extern __shared__ unsigned dynsm[];

    const int tid  = threadIdx.x;
    const int lane = tid & 31, warp = tid >> 5;
    const int wm = (warp >> 1) * 64;
    const int wn = (warp & 1) * 64;
    const int g = lane >> 2, tg = lane & 3;
    const int bm = blockIdx.y * BM, bn = blockIdx.x * BN;

    float acc[4][8][4];
    #pragma unroll
    for (int i = 0; i < 4; i++)
        #pragma unroll
        for (int j = 0; j < 8; j++)
            #pragma unroll
            for (int r = 0; r < 4; r++) acc[i][j][r] = 0.f;

    auto issue_tile = [&](int t, int st) {
        int kt = t * BK;
        unsigned* Ad = dynsm + st * SLOT;
        unsigned* Wd = Ad + ASZ;
        #pragma unroll
        for (int i = 0; i < 4; i++) {
            int f = tid + i * 128;
            cp16(&Ad[(f >> 2) * ASTRIDE + (f & 3) * 4],
                 &A[(size_t)(bm + (f >> 2)) * K + kt + (f & 3) * 4]);
        }
        #pragma unroll
        for (int i = 0; i < 4; i++) {
            int f = tid + i * 128;
            cp16(&Wd[(f >> 5) * WSTRIDE + (f & 31) * 4],
                 &W[(size_t)(kt + (f >> 5)) * N + bn + (f & 31) * 4]);
        }
        asm volatile("cp.async.commit_group;\n");
    };

    const int nt = K / BK;   // >= 32 always
    issue_tile(0, 0);
    issue_tile(1, 1);
    issue_tile(2, 2);

    for (int it = 0; it < nt; it++) {
        if (it + 2 < nt)      { asm volatile("cp.async.wait_group 2;\n"); }
        else if (it + 1 < nt) { asm volatile("cp.async.wait_group 1;\n"); }
        else                  { asm volatile("cp.async.wait_group 0;\n"); }
        __syncthreads();

        if (it + 3 < nt) issue_tile(it + 3, (it + 3) & 3);

        const unsigned* Asl = dynsm + (it & 3) * SLOT;
        const unsigned* Wsl = Asl + ASZ;

        #pragma unroll
        for (int ks = 0; ks < BK; ks += 8) {
            unsigned af[4][4], bf[8][2];
            #pragma unroll
            for (int mi = 0; mi < 4; mi++) {
                int r = wm + mi * 16 + g;
                af[mi][0] = Asl[r * ASTRIDE + ks + tg];
                af[mi][1] = Asl[(r + 8) * ASTRIDE + ks + tg];
                af[mi][2] = Asl[r * ASTRIDE + ks + tg + 4];
                af[mi][3] = Asl[(r + 8) * ASTRIDE + ks + tg + 4];
            }
            #pragma unroll
            for (int nj = 0; nj < 8; nj++) {
                int c = wn + nj * 8 + g;
                bf[nj][0] = Wsl[(ks + tg) * WSTRIDE + c];
                bf[nj][1] = Wsl[(ks + tg + 4) * WSTRIDE + c];
            }
            #pragma unroll
            for (int mi = 0; mi < 4; mi++)
                #pragma unroll
                for (int nj = 0; nj < 8; nj++)
                    mma_tf32(acc[mi][nj], af[mi], bf[nj]);
        }
    }

    #pragma unroll
    for (int mi = 0; mi < 4; mi++) {
        #pragma unroll
        for (int nj = 0; nj < 8; nj++) {
            int row = bm + wm + mi * 16 + g;
            int col = bn + wn + nj * 8 + tg * 2;
            float b0 = bias[col], b1 = bias[col + 1];
            float2 v0 = make_float2(acc[mi][nj][0] + b0, acc[mi][nj][1] + b1);
            float2 v1 = make_float2(acc[mi][nj][2] + b0, acc[mi][nj][3] + b1);
            if (ACT == 1) {
                v0.x = 0.5f * v0.x * (1.f + erff(v0.x * 0.7071067811865475f));
                v0.y = 0.5f * v0.y * (1.f + erff(v0.y * 0.7071067811865475f));
                v1.x = 0.5f * v1.x * (1.f + erff(v1.x * 0.7071067811865475f));
                v1.y = 0.5f * v1.y * (1.f + erff(v1.y * 0.7071067811865475f));
            }
            *(float2*)&C[(size_t)row * N + col]       = v0;
            *(float2*)&C[(size_t)(row + 8) * N + col] = v1;
        }
    }
}

// ---------------- fused attention: scores (+prev / +store S0) + online softmax + P@V ---
// CTA = 128 q-rows of one (b,h). 128 threads = 4 warps, each warp owns 32 q-rows
// (2 m-frags) -> K/V fragment LDS amortized over 2x mmas. K/V tiles (32x64) via
// cp.async double buffer; buffer 1 + P buffer overlay the retired Q staging tile.
// layer 0: writes raw scaled scores to outS. layer 1: reads prevS.
// (R12-verified: 172us, L1 57.6%)
__global__ __launch_bounds__(128)
void attn_fused(const float* __restrict__ QH, const float* __restrict__ KH,
                const float* __restrict__ VH, const float* __restrict__ scale,
                const float* __restrict__ extra, int layer,
                const float* __restrict__ prevS, float* __restrict__ outS,
                float* __restrict__ O)
{
    extern __shared__ unsigned dynsm[];
    unsigned* K0 = dynsm;
    unsigned* V0 = dynsm + KVW;
    unsigned* UB = dynsm + AUB;          // Q staging (128x72)
    unsigned* K1 = UB;                   // after Q retire
    unsigned* V1 = UB + KVW;
    unsigned* PsAll = dynsm + APS;       // 4 warps x 32x36

    const int tid = threadIdx.x;
    const int lane = tid & 31, warp = tid >> 5;
    const int g = lane >> 2, tg = lane & 3;
    const int wq = warp * 32;
    const int bh = blockIdx.y, b = bh >> 3, h = bh & 7;
    const int q0 = blockIdx.x * 128;
    const float* Qb = QH + (size_t)b * SQv * Dm + h * HDv;
    const float* Kb = KH + (size_t)b * SKv * Dm + h * HDv;
    const float* Vb = VH + (size_t)b * SKv * Dm + h * HDv;
    unsigned* Psw = PsAll + warp * (32 * 36);

    auto issue_kv = [&](int t, unsigned* Kd, unsigned* Vd) {
        int kt = t * 32;
        #pragma unroll
        for (int i = 0; i < 4; i++) {
            int f = tid + i * 128;
            int r = f >> 4, c = (f & 15) * 4;
            cp16(&Kd[r * 72 + c], &Kb[(size_t)(kt + r) * Dm + c]);
            cp16(&Vd[r * 72 + c], &Vb[(size_t)(kt + r) * Dm + c]);
        }
        asm volatile("cp.async.commit_group;\n");
    };

    // group 0: K/V tile 0; group 1: Q tile (128x64) -> UB
    issue_kv(0, K0, V0);
    #pragma unroll
    for (int i = 0; i < 16; i++) {
        int f = tid + i * 128;
        int r = f >> 4, c = (f & 15) * 4;
        cp16(&UB[r * 72 + c], &Qb[(size_t)(q0 + r) * Dm + c]);
    }
    asm volatile("cp.async.commit_group;\n");
    asm volatile("cp.async.wait_group 0;\n");
    __syncthreads();

    // stage Q fragments: 8 kc x 2 mi x 4 regs = 64 regs
    unsigned qf[8][2][4];
    #pragma unroll
    for (int kc = 0; kc < 8; kc++)
        #pragma unroll
        for (int mi = 0; mi < 2; mi++) {
            int r = (wq + mi * 16 + g) * 72;
            qf[kc][mi][0] = UB[r + kc * 8 + tg];
            qf[kc][mi][1] = UB[r + 8 * 72 + kc * 8 + tg];
            qf[kc][mi][2] = UB[r + kc * 8 + tg + 4];
            qf[kc][mi][3] = UB[r + 8 * 72 + kc * 8 + tg + 4];
        }
    __syncthreads();   // UB retired -> becomes K1/V1/Ps
    issue_kv(1, K1, V1);

    float e = extra[layer];
    e = fminf(fmaxf(e, 0.01f), 50.0f);
    const float eff = scale[layer] * e;

    float m[2][2], l[2][2];
    #pragma unroll
    for (int mi = 0; mi < 2; mi++) { m[mi][0] = -INFINITY; m[mi][1] = -INFINITY; l[mi][0] = 0.f; l[mi][1] = 0.f; }
    float oacc[2][8][4];
    #pragma unroll
    for (int mi = 0; mi < 2; mi++)
        #pragma unroll
        for (int j = 0; j < 8; j++)
            #pragma unroll
            for (int r = 0; r < 4; r++) oacc[mi][j][r] = 0.f;

    size_t srowA[2], srowB[2];
    #pragma unroll
    for (int mi = 0; mi < 2; mi++) {
        int rowA = q0 + wq + mi * 16 + g;
        srowA[mi] = ((size_t)bh * SQv + rowA) * SKv;
        srowB[mi] = srowA[mi] + (size_t)8 * SKv;
    }

    for (int it = 0; it < 32; it++) {
        const int kt = it * 32;
        unsigned* Kc = (it & 1) ? K1 : K0;
        unsigned* Vc = (it & 1) ? V1 : V0;

        if (it < 31) { asm volatile("cp.async.wait_group 1;\n"); }
        else         { asm volatile("cp.async.wait_group 0;\n"); }
        __syncthreads();

        // ---- scores: s[mi][nj] = Q(32) x K^T(32), d = 64 ----
        float s[2][4][4];
        #pragma unroll
        for (int mi = 0; mi < 2; mi++)
            #pragma unroll
            for (int j = 0; j < 4; j++)
                #pragma unroll
                for (int r = 0; r < 4; r++) s[mi][j][r] = 0.f;
        #pragma unroll
        for (int kc = 0; kc < 8; kc++) {
            unsigned bf[4][2];
            #pragma unroll
            for (int nj = 0; nj < 4; nj++) {
                int c = (nj * 8 + g) * 72;
                bf[nj][0] = Kc[c + kc * 8 + tg];
                bf[nj][1] = Kc[c + kc * 8 + tg + 4];
            }
            #pragma unroll
            for (int mi = 0; mi < 2; mi++)
                #pragma unroll
                for (int nj = 0; nj < 4; nj++)
                    mma_tf32(s[mi][nj], qf[kc][mi], bf[nj]);
        }

        // ---- scale, add prev / store raw scores ----
        if (prevS) {
            #pragma unroll
            for (int mi = 0; mi < 2; mi++)
                #pragma unroll
                for (int nj = 0; nj < 4; nj++) {
                    int col = kt + nj * 8 + tg * 2;
                    float2 p0 = *(const float2*)&prevS[srowA[mi] + col];
                    float2 p8 = *(const float2*)&prevS[srowB[mi] + col];
                    s[mi][nj][0] = fmaf(s[mi][nj][0], eff, p0.x);
                    s[mi][nj][1] = fmaf(s[mi][nj][1], eff, p0.y);
                    s[mi][nj][2] = fmaf(s[mi][nj][2], eff, p8.x);
                    s[mi][nj][3] = fmaf(s[mi][nj][3], eff, p8.y);
                }
        } else {
            #pragma unroll
            for (int mi = 0; mi < 2; mi++)
                #pragma unroll
                for (int nj = 0; nj < 4; nj++) {
                    s[mi][nj][0] *= eff; s[mi][nj][1] *= eff;
                    s[mi][nj][2] *= eff; s[mi][nj][3] *= eff;
                    int col = kt + nj * 8 + tg * 2;
                    *(float2*)&outS[srowA[mi] + col] = make_float2(s[mi][nj][0], s[mi][nj][1]);
                    *(float2*)&outS[srowB[mi] + col] = make_float2(s[mi][nj][2], s[mi][nj][3]);
                }
        }

        // ---- online softmax update (per mi, per half) ----
        #pragma unroll
        for (int mi = 0; mi < 2; mi++) {
            float tmA = -INFINITY, tmB = -INFINITY;
            #pragma unroll
            for (int nj = 0; nj < 4; nj++) {
                tmA = fmaxf(tmA, fmaxf(s[mi][nj][0], s[mi][nj][1]));
                tmB = fmaxf(tmB, fmaxf(s[mi][nj][2], s[mi][nj][3]));
            }
            tmA = fmaxf(tmA, __shfl_xor_sync(0xffffffffu, tmA, 1));
            tmA = fmaxf(tmA, __shfl_xor_sync(0xffffffffu, tmA, 2));
            tmB = fmaxf(tmB, __shfl_xor_sync(0xffffffffu, tmB, 1));
            tmB = fmaxf(tmB, __shfl_xor_sync(0xffffffffu, tmB, 2));

            float nmA = fmaxf(m[mi][0], tmA), nmB = fmaxf(m[mi][1], tmB);
            float cA = __expf(m[mi][0] - nmA), cB = __expf(m[mi][1] - nmB);
            float rsA = 0.f, rsB = 0.f;
            #pragma unroll
            for (int nj = 0; nj < 4; nj++) {
                s[mi][nj][0] = __expf(s[mi][nj][0] - nmA);
                s[mi][nj][1] = __expf(s[mi][nj][1] - nmA);
                s[mi][nj][2] = __expf(s[mi][nj][2] - nmB);
                s[mi][nj][3] = __expf(s[mi][nj][3] - nmB);
                rsA += s[mi][nj][0] + s[mi][nj][1];
                rsB += s[mi][nj][2] + s[mi][nj][3];
            }
            rsA += __shfl_xor_sync(0xffffffffu, rsA, 1);
            rsA += __shfl_xor_sync(0xffffffffu, rsA, 2);
            rsB += __shfl_xor_sync(0xffffffffu, rsB, 1);
            rsB += __shfl_xor_sync(0xffffffffu, rsB, 2);
            l[mi][0] = l[mi][0] * cA + rsA;  l[mi][1] = l[mi][1] * cB + rsB;
            m[mi][0] = nmA;  m[mi][1] = nmB;
            #pragma unroll
            for (int nj = 0; nj < 8; nj++) {
                oacc[mi][nj][0] *= cA; oacc[mi][nj][1] *= cA;
                oacc[mi][nj][2] *= cB; oacc[mi][nj][3] *= cB;
            }
        }

        // ---- P: C-layout -> smem (stride 36, read-conflict-free) -> A-layout ----
        #pragma unroll
        for (int mi = 0; mi < 2; mi++)
            #pragma unroll
            for (int nj = 0; nj < 4; nj++) {
                Psw[(mi * 16 + g) * 36 + nj * 8 + tg * 2]     = __float_as_uint(s[mi][nj][0]);
                Psw[(mi * 16 + g) * 36 + nj * 8 + tg * 2 + 1] = __float_as_uint(s[mi][nj][1]);
                Psw[(mi * 16 + 8 + g) * 36 + nj * 8 + tg * 2]     = __float_as_uint(s[mi][nj][2]);
                Psw[(mi * 16 + 8 + g) * 36 + nj * 8 + tg * 2 + 1] = __float_as_uint(s[mi][nj][3]);
            }
        __syncwarp();
        unsigned pf[4][2][4];
        #pragma unroll
        for (int kc = 0; kc < 4; kc++)
            #pragma unroll
            for (int mi = 0; mi < 2; mi++) {
                int r = (mi * 16 + g) * 36;
                pf[kc][mi][0] = Psw[r + kc * 8 + tg];
                pf[kc][mi][1] = Psw[r + 8 * 36 + kc * 8 + tg];
                pf[kc][mi][2] = Psw[r + kc * 8 + tg + 4];
                pf[kc][mi][3] = Psw[r + 8 * 36 + kc * 8 + tg + 4];
            }

        // ---- O += P(32x32) @ V(32x64) ----
        #pragma unroll
        for (int kc = 0; kc < 4; kc++) {
            unsigned vb[8][2];
            #pragma unroll
            for (int nj = 0; nj < 8; nj++) {
                int c = nj * 8 + g;
                vb[nj][0] = Vc[(kc * 8 + tg) * 72 + c];
                vb[nj][1] = Vc[(kc * 8 + tg + 4) * 72 + c];
            }
            #pragma unroll
            for (int mi = 0; mi < 2; mi++)
                #pragma unroll
                for (int nj = 0; nj < 8; nj++)
                    mma_tf32(oacc[mi][nj], pf[kc][mi], vb[nj]);
        }

        __syncthreads();   // all warps done reading Kc/Vc
        if (it + 2 < 32) issue_kv(it + 2, Kc, Vc);   // refill the just-freed buffer
    }

    // ---- finalize: O /= l, write [b, q, h*64 + d] ----
    float* Ob = O + (size_t)b * SQv * Dm + h * HDv;
    #pragma unroll
    for (int mi = 0; mi < 2; mi++) {
        float iA = 1.f / l[mi][0], iB = 1.f / l[mi][1];
        int rowA = q0 + wq + mi * 16 + g;
        #pragma unroll
        for (int nj = 0; nj < 8; nj++) {
            int col = nj * 8 + tg * 2;
            *(float2*)&Ob[(size_t)rowA * Dm + col] =
                make_float2(oacc[mi][nj][0] * iA, oacc[mi][nj][1] * iA);
            *(float2*)&Ob[(size_t)(rowA + 8) * Dm + col] =
                make_float2(oacc[mi][nj][2] * iB, oacc[mi][nj][3] * iB);
        }
    }
}

// ---------------- gated residual + post-LayerNorm ----------------------
__global__ __launch_bounds__(256)
void addnorm_kernel(const float* __restrict__ qin, float* __restrict__ qout,
                    const float* __restrict__ delta,
                    const float* __restrict__ gate, const float* __restrict__ g,
                    const float* __restrict__ bb)
{
    const size_t row = blockIdx.x;
    const int tid = threadIdx.x;
    const float gt = gate[0];
    const float sp = (gt > 20.f) ? gt : log1pf(expf(gt));   // softplus

    float2 x = *(const float2*)&qin[row * Dm + tid * 2];
    float2 dd = *(const float2*)&delta[row * Dm + tid * 2];
    float y0 = x.x + sp * dd.x;
    float y1 = x.y + sp * dd.y;

    float s = blk_sum256(y0 + y1);
    float mu = s * (1.f / 512.f);
    float s2 = blk_sum256((y0 - mu) * (y0 - mu) + (y1 - mu) * (y1 - mu));
    float inv = rsqrtf(s2 * (1.f / 512.f) + 1e-5f);

    float2 o;
    o.x = (y0 - mu) * inv * g[tid * 2 + 0] + bb[tid * 2 + 0];
    o.y = (y1 - mu) * inv * g[tid * 2 + 1] + bb[tid * 2 + 1];
    *(float2*)&qout[row * Dm + tid * 2] = o;
}

// ---------------- launcher -------------------------------------------------------------
extern "C" void kernel_launch(void* const* d_in, const int* in_sizes, int n_in,
                              void* d_out, int out_size)
{
    (void)in_sizes; (void)n_in; (void)out_size;
    const float* q_in  = (const float*)d_in[0];
    const float* k_in  = (const float*)d_in[1];
    const float* v_in  = (const float*)d_in[2];
    const float* WQ    = (const float*)d_in[3];
    const float* bQ    = (const float*)d_in[4];
    const float* WK    = (const float*)d_in[5];
    const float* bK    = (const float*)d_in[6];
    const float* WV    = (const float*)d_in[7];
    const float* bV    = (const float*)d_in[8];
    const float* WO    = (const float*)d_in[9];
    const float* bO    = (const float*)d_in[10];
    const float* Wf1   = (const float*)d_in[11];
    const float* bf1   = (const float*)d_in[12];
    const float* Wf2   = (const float*)d_in[13];
    const float* bf2   = (const float*)d_in[14];
    const float* ln1g  = (const float*)d_in[15];
    const float* ln1b  = (const float*)d_in[16];
    const float* ln2g  = (const float*)d_in[17];
    const float* ln2b  = (const float*)d_in[18];
    const float* scale = (const float*)d_in[19];
    const float* extra = (const float*)d_in[20];
    const float* gA    = (const float*)d_in[21];
    const float* gF    = (const float*)d_in[22];

    float *QH, *KH, *VH, *ATT, *F1, *S0;
    cudaGetSymbolAddress((void**)&QH, g_QH);
    cudaGetSymbolAddress((void**)&KH, g_KH);
    cudaGetSymbolAddress((void**)&VH, g_VH);
    cudaGetSymbolAddress((void**)&ATT, g_ATT);
    cudaGetSymbolAddress((void**)&F1, g_F1);
    cudaGetSymbolAddress((void**)&S0, g_S0);

    // opt-in to >48KB dynamic smem (host state, capture-safe)
    cudaFuncSetAttribute(gemm_tf32<0>, cudaFuncAttributeMaxDynamicSharedMemorySize, GEMM_SMEM);
    cudaFuncSetAttribute(gemm_tf32<1>, cudaFuncAttributeMaxDynamicSharedMemorySize, GEMM_SMEM);
    cudaFuncSetAttribute(attn_fused,   cudaFuncAttributeMaxDynamicSharedMemorySize, ATTN_SMEM);

    float* qbuf = (float*)d_out;   // q lives in d_out after the first addnorm

    const dim3 gP(Dm / BN, Mrows / BM);        // (4, 64)  N=512 GEMMs
    const dim3 gF1(DFFv / BN, Mrows / BM);     // (16, 64) FFN1

    for (int i = 0; i < 2; i++) {
        const size_t wofD = (size_t)i * Dm * Dm;
        const size_t wofF = (size_t)i * Dm * DFFv;
        const float* qcur = (i == 0) ? q_in : qbuf;   // layer-0 reads the input directly

        gemm_tf32<0><<<gP, 128, GEMM_SMEM>>>(qcur, WQ + wofD, bQ + i * Dm, QH, Mrows, Dm, Dm);
        gemm_tf32<0><<<gP, 128, GEMM_SMEM>>>(k_in, WK + wofD, bK + i * Dm, KH, Mrows, Dm, Dm);
        gemm_tf32<0><<<gP, 128, GEMM_SMEM>>>(v_in, WV + wofD, bV + i * Dm, VH, Mrows, Dm, Dm);

        // fused scores(+prev/S0) + online softmax + P@V; attn-out overwrites QH
        const float* prev = (i == 0) ? nullptr : S0;
        float* Sout = (i == 0) ? S0 : nullptr;
        attn_fused<<<dim3(SQv / 128, Bz * Hh), 128, ATTN_SMEM>>>(QH, KH, VH, scale, extra, i,
                                                                 prev, Sout, QH);

        gemm_tf32<0><<<gP, 128, GEMM_SMEM>>>(QH, WO + wofD, bO + i * Dm, ATT, Mrows, Dm, Dm);
        addnorm_kernel<<<Mrows, 256>>>(qcur, qbuf, ATT, gA + i,
                                       ln1g + (size_t)i * Dm, ln1b + (size_t)i * Dm);

        gemm_tf32<1><<<gF1, 128, GEMM_SMEM>>>(qbuf, Wf1 + wofF, bf1 + i * DFFv, F1, Mrows, DFFv, Dm);
        gemm_tf32<0><<<gP, 128, GEMM_SMEM>>>(F1, Wf2 + wofF, bf2 + i * Dm, ATT, Mrows, Dm, DFFv);
        addnorm_kernel<<<Mrows, 256>>>(qbuf, qbuf, ATT, gF + i,
                                       ln2g + (size_t)i * Dm, ln2b + (size_t)i * Dm);
    }
}

// round 17
// speedup vs baseline: 1.3066x; 1.2374x over previous
#include <cuda_runtime.h>
#include <cuda_fp16.h>
#include <math.h>
#include <stdint.h>

// Problem constants
#define Bz   8
#define SQv  1024
#define SKv  1024
#define Dm   512
#define Hh   8
#define HDv  64
#define DFFv 2048
#define Mrows 8192   // B*SQ == B*SK

// ---- fp16 dense GEMM tiling ----------------------------------------------------------
// CTA 128x128, BK=32 halves. A and B tiles both [row][k] fp16, row stride 40 halves
// (20 words) -> fragment-load bank = (20g+tg)%32, all 32 distinct.
#define HSTRIDE_W 20                 // words per tile row
#define HTILE_W  (128 * HSTRIDE_W)   // 2560 words per matrix tile
#define HSLOT    (2 * HTILE_W)       // 5120 words per pipeline stage
#define GEMM_SMEM (4 * HSLOT * 4)    // 81920 bytes (4 stages)

// attn smem layout (words): K0,V0 (32x72 each) | UB (128x72, later K1|V1|Ps)
#define KVW  (32 * 72)
#define AUB  (2 * KVW)
#define UBW  (128 * 72)
#define APS  (AUB + 2 * KVW)
#define ATTN_SMEM ((2 * KVW + UBW) * 4)   // 55296 bytes

// ---------------- scratch (static device memory; no runtime allocation) ----------------
__device__ float  g_QH[4194304];     // [8192,512]
__device__ float  g_KH[4194304];
__device__ float  g_VH[4194304];
__device__ float  g_ATT[4194304];
__device__ float  g_S0[67108864];    // layer-0 pre-softmax scores
__device__ __half g_X16[4194304];    // fp16 copy of current q / FFN input
__device__ __half g_K16[4194304];
__device__ __half g_V16[4194304];
__device__ __half g_O16[4194304];    // attn output (fp16, feeds O-proj)
__device__ __half g_F1h[16777216];   // FFN1 output (fp16, feeds FFN2)
__device__ __half g_WT16[6291456];   // transposed fp16 weights [N,K]

// half-element offsets into g_WT16
#define OFF_WQ 0
#define OFF_WK 524288
#define OFF_WV 1048576
#define OFF_WO 1572864
#define OFF_W1 2097152   // [2][2048,512]
#define OFF_W2 4194304   // [2][512,2048]

// ---------------- mma / cp.async helpers ----------------------------------------------
__device__ __forceinline__ void mma_tf32(float c[4], const unsigned a[4], const unsigned b[2]) {
    asm volatile(
        "mma.sync.aligned.m16n8k8.row.col.f32.tf32.tf32.f32 "
        "{%0,%1,%2,%3}, {%4,%5,%6,%7}, {%8,%9}, {%0,%1,%2,%3};\n"
        : "+f"(c[0]), "+f"(c[1]), "+f"(c[2]), "+f"(c[3])
        : "r"(a[0]), "r"(a[1]), "r"(a[2]), "r"(a[3]), "r"(b[0]), "r"(b[1]));
}

__device__ __forceinline__ void mma_f16(float c[4], const unsigned a[4], const unsigned b[2]) {
    asm volatile(
        "mma.sync.aligned.m16n8k16.row.col.f32.f16.f16.f32 "
        "{%0,%1,%2,%3}, {%4,%5,%6,%7}, {%8,%9}, {%0,%1,%2,%3};\n"
        : "+f"(c[0]), "+f"(c[1]), "+f"(c[2]), "+f"(c[3])
        : "r"(a[0]), "r"(a[1]), "r"(a[2]), "r"(a[3]), "r"(b[0]), "r"(b[1]));
}

__device__ __forceinline__ void cp16(void* smem, const void* gmem) {
    unsigned saddr = (unsigned)__cvta_generic_to_shared(smem);
    asm volatile("cp.async.cg.shared.global [%0], [%1], 16;\n" :: "r"(saddr), "l"(gmem));
}

// ---------------- block reductions (blockDim.x == 256 assumed) ----------------
__device__ __forceinline__ float blk_sum256(float v) {
    __shared__ float s[8];
    int tid = threadIdx.x;
    #pragma unroll
    for (int o = 16; o > 0; o >>= 1) v += __shfl_xor_sync(0xffffffffu, v, o);
    __syncthreads();
    if ((tid & 31) == 0) s[tid >> 5] = v;
    __syncthreads();
    float r = 0.f;
    #pragma unroll
    for (int i = 0; i < 8; i++) r += s[i];
    return r;
}

// ---------------- fp32 -> fp16 convert (vectorized) ------------------------------------
__global__ __launch_bounds__(256)
void cvt_f2h(const float* __restrict__ in, __half* __restrict__ out)
{
    int i = (blockIdx.x * 256 + threadIdx.x) * 4;
    float4 v = *(const float4*)&in[i];
    *(__half2*)&out[i]     = __floats2half2_rn(v.x, v.y);
    *(__half2*)&out[i + 2] = __floats2half2_rn(v.z, v.w);
}

// ---------------- weight transpose: out16[z][n][k] = (half)in[z][k][n] ------------------
__global__ __launch_bounds__(256)
void transpose_kn_h(const float* __restrict__ in, __half* __restrict__ out, int K, int N)
{
    __shared__ float t[32][33];
    const int n0 = blockIdx.x * 32, k0 = blockIdx.y * 32;
    const size_t zo = (size_t)blockIdx.z * K * N;
    #pragma unroll
    for (int i = threadIdx.y; i < 32; i += 8)
        t[i][threadIdx.x] = in[zo + (size_t)(k0 + i) * N + n0 + threadIdx.x];
    __syncthreads();
    #pragma unroll
    for (int i = threadIdx.y; i < 32; i += 8)
        out[zo + (size_t)(n0 + i) * K + k0 + threadIdx.x] = __float2half_rn(t[threadIdx.x][i]);
}

// ---------------- fp16 dense GEMM: C = A[M,K] @ BT[N,K]^T + bias (+GELU) ---------------
// 128 threads = 4 warps (2x2), warp tile 64x64, m16n8k16 mma, BK=32 halves,
// 4-slot / 3-outstanding cp.async pipeline, ONE __syncthreads per K-step.
// OUT16: write fp16 C (for outputs consumed only by another GEMM's A-side).
template<int ACT, int OUT16>
__global__ __launch_bounds__(128)
void gemm_h(const __half* __restrict__ A, const __half* __restrict__ BT,
            const float* __restrict__ bias, void* __restrict__ Cout,
            int M, int N, int K)
{
    extern __shared__ unsigned dynsm[];

    const int tid  = threadIdx.x;
    const int lane = tid & 31, warp = tid >> 5;
    const int wm = (warp >> 1) * 64;
    const int wn = (warp & 1) * 64;
    const int g = lane >> 2, tg = lane & 3;
    const int bm = blockIdx.y * 128, bn = blockIdx.x * 128;

    float acc[4][8][4];
    #pragma unroll
    for (int i = 0; i < 4; i++)
        #pragma unroll
        for (int j = 0; j < 8; j++)
            #pragma unroll
            for (int r = 0; r < 4; r++) acc[i][j][r] = 0.f;

    auto issue_tile = [&](int t, int st) {
        const int kt = t * 32;                    // half offset in K
        unsigned* Ad = dynsm + st * HSLOT;
        unsigned* Bd = Ad + HTILE_W;
        // each matrix tile: 128 rows x 64B = 512 x 16B chunks; 4 per thread per matrix
        #pragma unroll
        for (int i = 0; i < 4; i++) {
            int f = tid + i * 128;
            int r = f >> 2, ch = f & 3;           // ch*8 halves = ch*16 bytes
            cp16(&Ad[r * HSTRIDE_W + ch * 4], &A[(size_t)(bm + r) * K + kt + ch * 8]);
            cp16(&Bd[r * HSTRIDE_W + ch * 4], &BT[(size_t)(bn + r) * K + kt + ch * 8]);
        }
        asm volatile("cp.async.commit_group;\n");
    };

    const int nt = K / 32;    // 16 (K=512) or 64 (K=2048)
    issue_tile(0, 0);
    issue_tile(1, 1);
    issue_tile(2, 2);

    for (int it = 0; it < nt; it++) {
        if (it + 2 < nt)      { asm volatile("cp.async.wait_group 2;\n"); }
        else if (it + 1 < nt) { asm volatile("cp.async.wait_group 1;\n"); }
        else                  { asm volatile("cp.async.wait_group 0;\n"); }
        __syncthreads();

        if (it + 3 < nt) issue_tile(it + 3, (it + 3) & 3);

        const unsigned* Asl = dynsm + (it & 3) * HSLOT;
        const unsigned* Bsl = Asl + HTILE_W;

        #pragma unroll
        for (int kc = 0; kc < 2; kc++) {          // two k16 chunks per 32-half tile
            unsigned af[4][4], bf[8][2];
            #pragma unroll
            for (int mi = 0; mi < 4; mi++) {
                int r = (wm + mi * 16 + g) * HSTRIDE_W;
                int r8 = r + 8 * HSTRIDE_W;
                af[mi][0] = Asl[r  + kc * 8 + tg];
                af[mi][1] = Asl[r8 + kc * 8 + tg];
                af[mi][2] = Asl[r  + kc * 8 + tg + 4];
                af[mi][3] = Asl[r8 + kc * 8 + tg + 4];
            }
            #pragma unroll
            for (int nj = 0; nj < 8; nj++) {
                int c = (wn + nj * 8 + g) * HSTRIDE_W;
                bf[nj][0] = Bsl[c + kc * 8 + tg];
                bf[nj][1] = Bsl[c + kc * 8 + tg + 4];
            }
            #pragma unroll
            for (int mi = 0; mi < 4; mi++)
                #pragma unroll
                for (int nj = 0; nj < 8; nj++)
                    mma_f16(acc[mi][nj], af[mi], bf[nj]);
        }
    }

    #pragma unroll
    for (int mi = 0; mi < 4; mi++) {
        #pragma unroll
        for (int nj = 0; nj < 8; nj++) {
            int row = bm + wm + mi * 16 + g;
            int col = bn + wn + nj * 8 + tg * 2;
            float b0 = bias[col], b1 = bias[col + 1];
            float2 v0 = make_float2(acc[mi][nj][0] + b0, acc[mi][nj][1] + b1);
            float2 v1 = make_float2(acc[mi][nj][2] + b0, acc[mi][nj][3] + b1);
            if (ACT == 1) {
                v0.x = 0.5f * v0.x * (1.f + erff(v0.x * 0.7071067811865475f));
                v0.y = 0.5f * v0.y * (1.f + erff(v0.y * 0.7071067811865475f));
                v1.x = 0.5f * v1.x * (1.f + erff(v1.x * 0.7071067811865475f));
                v1.y = 0.5f * v1.y * (1.f + erff(v1.y * 0.7071067811865475f));
            }
            if (OUT16) {
                __half* C16 = (__half*)Cout;
                *(__half2*)&C16[(size_t)row * N + col]       = __floats2half2_rn(v0.x, v0.y);
                *(__half2*)&C16[(size_t)(row + 8) * N + col] = __floats2half2_rn(v1.x, v1.y);
            } else {
                float* Cf = (float*)Cout;
                *(float2*)&Cf[(size_t)row * N + col]       = v0;
                *(float2*)&Cf[(size_t)(row + 8) * N + col] = v1;
            }
        }
    }
}

// ---------------- fused attention (R12-verified math; fp16 output) ----------------------
__global__ __launch_bounds__(128)
void attn_fused(const float* __restrict__ QH, const float* __restrict__ KH,
                const float* __restrict__ VH, const float* __restrict__ scale,
                const float* __restrict__ extra, int layer,
                const float* __restrict__ prevS, float* __restrict__ outS,
                __half* __restrict__ O16)
{
    extern __shared__ unsigned dynsm[];
    unsigned* K0 = dynsm;
    unsigned* V0 = dynsm + KVW;
    unsigned* UB = dynsm + AUB;
    unsigned* K1 = UB;
    unsigned* V1 = UB + KVW;
    unsigned* PsAll = dynsm + APS;

    const int tid = threadIdx.x;
    const int lane = tid & 31, warp = tid >> 5;
    const int g = lane >> 2, tg = lane & 3;
    const int wq = warp * 32;
    const int bh = blockIdx.y, b = bh >> 3, h = bh & 7;
    const int q0 = blockIdx.x * 128;
    const float* Qb = QH + (size_t)b * SQv * Dm + h * HDv;
    const float* Kb = KH + (size_t)b * SKv * Dm + h * HDv;
    const float* Vb = VH + (size_t)b * SKv * Dm + h * HDv;
    unsigned* Psw = PsAll + warp * (32 * 36);

    auto issue_kv = [&](int t, unsigned* Kd, unsigned* Vd) {
        int kt = t * 32;
        #pragma unroll
        for (int i = 0; i < 4; i++) {
            int f = tid + i * 128;
            int r = f >> 4, c = (f & 15) * 4;
            cp16(&Kd[r * 72 + c], &Kb[(size_t)(kt + r) * Dm + c]);
            cp16(&Vd[r * 72 + c], &Vb[(size_t)(kt + r) * Dm + c]);
        }
        asm volatile("cp.async.commit_group;\n");
    };

    issue_kv(0, K0, V0);
    #pragma unroll
    for (int i = 0; i < 16; i++) {
        int f = tid + i * 128;
        int r = f >> 4, c = (f & 15) * 4;
        cp16(&UB[r * 72 + c], &Qb[(size_t)(q0 + r) * Dm + c]);
    }
    asm volatile("cp.async.commit_group;\n");
    asm volatile("cp.async.wait_group 0;\n");
    __syncthreads();

    unsigned qf[8][2][4];
    #pragma unroll
    for (int kc = 0; kc < 8; kc++)
        #pragma unroll
        for (int mi = 0; mi < 2; mi++) {
            int r = (wq + mi * 16 + g) * 72;
            qf[kc][mi][0] = UB[r + kc * 8 + tg];
            qf[kc][mi][1] = UB[r + 8 * 72 + kc * 8 + tg];
            qf[kc][mi][2] = UB[r + kc * 8 + tg + 4];
            qf[kc][mi][3] = UB[r + 8 * 72 + kc * 8 + tg + 4];
        }
    __syncthreads();
    issue_kv(1, K1, V1);

    float e = extra[layer];
    e = fminf(fmaxf(e, 0.01f), 50.0f);
    const float eff = scale[layer] * e;

    float m[2][2], l[2][2];
    #pragma unroll
    for (int mi = 0; mi < 2; mi++) { m[mi][0] = -INFINITY; m[mi][1] = -INFINITY; l[mi][0] = 0.f; l[mi][1] = 0.f; }
    float oacc[2][8][4];
    #pragma unroll
    for (int mi = 0; mi < 2; mi++)
        #pragma unroll
        for (int j = 0; j < 8; j++)
            #pragma unroll
            for (int r = 0; r < 4; r++) oacc[mi][j][r] = 0.f;

    size_t srowA[2], srowB[2];
    #pragma unroll
    for (int mi = 0; mi < 2; mi++) {
        int rowA = q0 + wq + mi * 16 + g;
        srowA[mi] = ((size_t)bh * SQv + rowA) * SKv;
        srowB[mi] = srowA[mi] + (size_t)8 * SKv;
    }

    for (int it = 0; it < 32; it++) {
        const int kt = it * 32;
        unsigned* Kc = (it & 1) ? K1 : K0;
        unsigned* Vc = (it & 1) ? V1 : V0;

        if (it < 31) { asm volatile("cp.async.wait_group 1;\n"); }
        else         { asm volatile("cp.async.wait_group 0;\n"); }
        __syncthreads();

        float s[2][4][4];
        #pragma unroll
        for (int mi = 0; mi < 2; mi++)
            #pragma unroll
            for (int j = 0; j < 4; j++)
                #pragma unroll
                for (int r = 0; r < 4; r++) s[mi][j][r] = 0.f;
        #pragma unroll
        for (int kc = 0; kc < 8; kc++) {
            unsigned bf[4][2];
            #pragma unroll
            for (int nj = 0; nj < 4; nj++) {
                int c = (nj * 8 + g) * 72;
                bf[nj][0] = Kc[c + kc * 8 + tg];
                bf[nj][1] = Kc[c + kc * 8 + tg + 4];
            }
            #pragma unroll
            for (int mi = 0; mi < 2; mi++)
                #pragma unroll
                for (int nj = 0; nj < 4; nj++)
                    mma_tf32(s[mi][nj], qf[kc][mi], bf[nj]);
        }

        if (prevS) {
            #pragma unroll
            for (int mi = 0; mi < 2; mi++)
                #pragma unroll
                for (int nj = 0; nj < 4; nj++) {
                    int col = kt + nj * 8 + tg * 2;
                    float2 p0 = *(const float2*)&prevS[srowA[mi] + col];
                    float2 p8 = *(const float2*)&prevS[srowB[mi] + col];
                    s[mi][nj][0] = fmaf(s[mi][nj][0], eff, p0.x);
                    s[mi][nj][1] = fmaf(s[mi][nj][1], eff, p0.y);
                    s[mi][nj][2] = fmaf(s[mi][nj][2], eff, p8.x);
                    s[mi][nj][3] = fmaf(s[mi][nj][3], eff, p8.y);
                }
        } else {
            #pragma unroll
            for (int mi = 0; mi < 2; mi++)
                #pragma unroll
                for (int nj = 0; nj < 4; nj++) {
                    s[mi][nj][0] *= eff; s[mi][nj][1] *= eff;
                    s[mi][nj][2] *= eff; s[mi][nj][3] *= eff;
                    int col = kt + nj * 8 + tg * 2;
                    *(float2*)&outS[srowA[mi] + col] = make_float2(s[mi][nj][0], s[mi][nj][1]);
                    *(float2*)&outS[srowB[mi] + col] = make_float2(s[mi][nj][2], s[mi][nj][3]);
                }
        }

        #pragma unroll
        for (int mi = 0; mi < 2; mi++) {
            float tmA = -INFINITY, tmB = -INFINITY;
            #pragma unroll
            for (int nj = 0; nj < 4; nj++) {
                tmA = fmaxf(tmA, fmaxf(s[mi][nj][0], s[mi][nj][1]));
                tmB = fmaxf(tmB, fmaxf(s[mi][nj][2], s[mi][nj][3]));
            }
            tmA = fmaxf(tmA, __shfl_xor_sync(0xffffffffu, tmA, 1));
            tmA = fmaxf(tmA, __shfl_xor_sync(0xffffffffu, tmA, 2));
            tmB = fmaxf(tmB, __shfl_xor_sync(0xffffffffu, tmB, 1));
            tmB = fmaxf(tmB, __shfl_xor_sync(0xffffffffu, tmB, 2));

            float nmA = fmaxf(m[mi][0], tmA), nmB = fmaxf(m[mi][1], tmB);
            float cA = __expf(m[mi][0] - nmA), cB = __expf(m[mi][1] - nmB);
            float rsA = 0.f, rsB = 0.f;
            #pragma unroll
            for (int nj = 0; nj < 4; nj++) {
                s[mi][nj][0] = __expf(s[mi][nj][0] - nmA);
                s[mi][nj][1] = __expf(s[mi][nj][1] - nmA);
                s[mi][nj][2] = __expf(s[mi][nj][2] - nmB);
                s[mi][nj][3] = __expf(s[mi][nj][3] - nmB);
                rsA += s[mi][nj][0] + s[mi][nj][1];
                rsB += s[mi][nj][2] + s[mi][nj][3];
            }
            rsA += __shfl_xor_sync(0xffffffffu, rsA, 1);
            rsA += __shfl_xor_sync(0xffffffffu, rsA, 2);
            rsB += __shfl_xor_sync(0xffffffffu, rsB, 1);
            rsB += __shfl_xor_sync(0xffffffffu, rsB, 2);
            l[mi][0] = l[mi][0] * cA + rsA;  l[mi][1] = l[mi][1] * cB + rsB;
            m[mi][0] = nmA;  m[mi][1] = nmB;
            #pragma unroll
            for (int nj = 0; nj < 8; nj++) {
                oacc[mi][nj][0] *= cA; oacc[mi][nj][1] *= cA;
                oacc[mi][nj][2] *= cB; oacc[mi][nj][3] *= cB;
            }
        }

        #pragma unroll
        for (int mi = 0; mi < 2; mi++)
            #pragma unroll
            for (int nj = 0; nj < 4; nj++) {
                Psw[(mi * 16 + g) * 36 + nj * 8 + tg * 2]     = __float_as_uint(s[mi][nj][0]);
                Psw[(mi * 16 + g) * 36 + nj * 8 + tg * 2 + 1] = __float_as_uint(s[mi][nj][1]);
                Psw[(mi * 16 + 8 + g) * 36 + nj * 8 + tg * 2]     = __float_as_uint(s[mi][nj][2]);
                Psw[(mi * 16 + 8 + g) * 36 + nj * 8 + tg * 2 + 1] = __float_as_uint(s[mi][nj][3]);
            }
        __syncwarp();
        unsigned pf[4][2][4];
        #pragma unroll
        for (int kc = 0; kc < 4; kc++)
            #pragma unroll
            for (int mi = 0; mi < 2; mi++) {
                int r = (mi * 16 + g) * 36;
                pf[kc][mi][0] = Psw[r + kc * 8 + tg];
                pf[kc][mi][1] = Psw[r + 8 * 36 + kc * 8 + tg];
                pf[kc][mi][2] = Psw[r + kc * 8 + tg + 4];
                pf[kc][mi][3] = Psw[r + 8 * 36 + kc * 8 + tg + 4];
            }

        #pragma unroll
        for (int kc = 0; kc < 4; kc++) {
            unsigned vb[8][2];
            #pragma unroll
            for (int nj = 0; nj < 8; nj++) {
                int c = nj * 8 + g;
                vb[nj][0] = Vc[(kc * 8 + tg) * 72 + c];
                vb[nj][1] = Vc[(kc * 8 + tg + 4) * 72 + c];
            }
            #pragma unroll
            for (int mi = 0; mi < 2; mi++)
                #pragma unroll
                for (int nj = 0; nj < 8; nj++)
                    mma_tf32(oacc[mi][nj], pf[kc][mi], vb[nj]);
        }

        __syncthreads();
        if (it + 2 < 32) issue_kv(it + 2, Kc, Vc);
    }

    // finalize: O /= l, write fp16 [b, q, h*64 + d]
    __half* Ob = O16 + (size_t)b * SQv * Dm + h * HDv;
    #pragma unroll
    for (int mi = 0; mi < 2; mi++) {
        float iA = 1.f / l[mi][0], iB = 1.f / l[mi][1];
        int rowA = q0 + wq + mi * 16 + g;
        #pragma unroll
        for (int nj = 0; nj < 8; nj++) {
            int col = nj * 8 + tg * 2;
            *(__half2*)&Ob[(size_t)rowA * Dm + col] =
                __floats2half2_rn(oacc[mi][nj][0] * iA, oacc[mi][nj][1] * iA);
            *(__half2*)&Ob[(size_t)(rowA + 8) * Dm + col] =
                __floats2half2_rn(oacc[mi][nj][2] * iB, oacc[mi][nj][3] * iB);
        }
    }
}

// ---------------- gated residual + post-LayerNorm (dual fp32+fp16 output) --------------
__global__ __launch_bounds__(256)
void addnorm_kernel(const float* __restrict__ qin, float* __restrict__ qout,
                    __half* __restrict__ out16, const float* __restrict__ delta,
                    const float* __restrict__ gate, const float* __restrict__ g,
                    const float* __restrict__ bb)
{
    const size_t row = blockIdx.x;
    const int tid = threadIdx.x;
    const float gt = gate[0];
    const float sp = (gt > 20.f) ? gt : log1pf(expf(gt));   // softplus

    float2 x = *(const float2*)&qin[row * Dm + tid * 2];
    float2 dd = *(const float2*)&delta[row * Dm + tid * 2];
    float y0 = x.x + sp * dd.x;
    float y1 = x.y + sp * dd.y;

    float s = blk_sum256(y0 + y1);
    float mu = s * (1.f / 512.f);
    float s2 = blk_sum256((y0 - mu) * (y0 - mu) + (y1 - mu) * (y1 - mu));
    float inv = rsqrtf(s2 * (1.f / 512.f) + 1e-5f);

    float2 o;
    o.x = (y0 - mu) * inv * g[tid * 2 + 0] + bb[tid * 2 + 0];
    o.y = (y1 - mu) * inv * g[tid * 2 + 1] + bb[tid * 2 + 1];
    *(float2*)&qout[row * Dm + tid * 2] = o;
    *(__half2*)&out16[row * Dm + tid * 2] = __floats2half2_rn(o.x, o.y);
}

// ---------------- launcher -------------------------------------------------------------
extern "C" void kernel_launch(void* const* d_in, const int* in_sizes, int n_in,
                              void* d_out, int out_size)
{
    (void)in_sizes; (void)n_in; (void)out_size;
    const float* q_in  = (const float*)d_in[0];
    const float* k_in  = (const float*)d_in[1];
    const float* v_in  = (const float*)d_in[2];
    const float* WQ    = (const float*)d_in[3];
    const float* bQ    = (const float*)d_in[4];
    const float* WK    = (const float*)d_in[5];
    const float* bK    = (const float*)d_in[6];
    const float* WV    = (const float*)d_in[7];
    const float* bV    = (const float*)d_in[8];
    const float* WO    = (const float*)d_in[9];
    const float* bO    = (const float*)d_in[10];
    const float* Wf1   = (const float*)d_in[11];
    const float* bf1   = (const float*)d_in[12];
    const float* Wf2   = (const float*)d_in[13];
    const float* bf2   = (const float*)d_in[14];
    const float* ln1g  = (const float*)d_in[15];
    const float* ln1b  = (const float*)d_in[16];
    const float* ln2g  = (const float*)d_in[17];
    const float* ln2b  = (const float*)d_in[18];
    const float* scale = (const float*)d_in[19];
    const float* extra = (const float*)d_in[20];
    const float* gA    = (const float*)d_in[21];
    const float* gF    = (const float*)d_in[22];

    float *QH, *KH, *VH, *ATT, *S0;
    __half *X16, *K16, *V16, *O16, *F1h, *WT16;
    cudaGetSymbolAddress((void**)&QH, g_QH);
    cudaGetSymbolAddress((void**)&KH, g_KH);
    cudaGetSymbolAddress((void**)&VH, g_VH);
    cudaGetSymbolAddress((void**)&ATT, g_ATT);
    cudaGetSymbolAddress((void**)&S0, g_S0);
    cudaGetSymbolAddress((void**)&X16, g_X16);
    cudaGetSymbolAddress((void**)&K16, g_K16);
    cudaGetSymbolAddress((void**)&V16, g_V16);
    cudaGetSymbolAddress((void**)&O16, g_O16);
    cudaGetSymbolAddress((void**)&F1h, g_F1h);
    cudaGetSymbolAddress((void**)&WT16, g_WT16);

    cudaFuncSetAttribute(gemm_h<0,0>, cudaFuncAttributeMaxDynamicSharedMemorySize, GEMM_SMEM);
    cudaFuncSetAttribute(gemm_h<1,1>, cudaFuncAttributeMaxDynamicSharedMemorySize, GEMM_SMEM);
    cudaFuncSetAttribute(attn_fused,  cudaFuncAttributeMaxDynamicSharedMemorySize, ATTN_SMEM);

    // ---- one-time prep: fp16 inputs + transposed fp16 weights ----
    cvt_f2h<<<4096, 256>>>(q_in, X16);
    cvt_f2h<<<4096, 256>>>(k_in, K16);
    cvt_f2h<<<4096, 256>>>(v_in, V16);
    const dim3 tb(32, 8);
    transpose_kn_h<<<dim3(16, 16, 2), tb>>>(WQ,  WT16 + OFF_WQ, 512, 512);
    transpose_kn_h<<<dim3(16, 16, 2), tb>>>(WK,  WT16 + OFF_WK, 512, 512);
    transpose_kn_h<<<dim3(16, 16, 2), tb>>>(WV,  WT16 + OFF_WV, 512, 512);
    transpose_kn_h<<<dim3(16, 16, 2), tb>>>(WO,  WT16 + OFF_WO, 512, 512);
    transpose_kn_h<<<dim3(64, 16, 2), tb>>>(Wf1, WT16 + OFF_W1, 512, 2048);
    transpose_kn_h<<<dim3(16, 64, 2), tb>>>(Wf2, WT16 + OFF_W2, 2048, 512);

    float* qbuf = (float*)d_out;   // q lives in d_out after the first addnorm

    const dim3 gP(Dm / 128, Mrows / 128);      // (4, 64)
    const dim3 gF1g(DFFv / 128, Mrows / 128);  // (16, 64)

    for (int i = 0; i < 2; i++) {
        const float* qcur = (i == 0) ? q_in : qbuf;
        const __half* WTq = WT16 + OFF_WQ + (size_t)i * 262144;
        const __half* WTk = WT16 + OFF_WK + (size_t)i * 262144;
        const __half* WTv = WT16 + OFF_WV + (size_t)i * 262144;
        const __half* WTo = WT16 + OFF_WO + (size_t)i * 262144;
        const __half* WT1 = WT16 + OFF_W1 + (size_t)i * 1048576;
        const __half* WT2 = WT16 + OFF_W2 + (size_t)i * 1048576;

        gemm_h<0,0><<<gP, 128, GEMM_SMEM>>>(X16, WTq, bQ + i * Dm, QH, Mrows, Dm, Dm);
        gemm_h<0,0><<<gP, 128, GEMM_SMEM>>>(K16, WTk, bK + i * Dm, KH, Mrows, Dm, Dm);
        gemm_h<0,0><<<gP, 128, GEMM_SMEM>>>(V16, WTv, bV + i * Dm, VH, Mrows, Dm, Dm);

        const float* prev = (i == 0) ? nullptr : S0;
        float* Sout = (i == 0) ? S0 : nullptr;
        attn_fused<<<dim3(SQv / 128, Bz * Hh), 128, ATTN_SMEM>>>(QH, KH, VH, scale, extra, i,
                                                                 prev, Sout, O16);

        gemm_h<0,0><<<gP, 128, GEMM_SMEM>>>(O16, WTo, bO + i * Dm, ATT, Mrows, Dm, Dm);
        addnorm_kernel<<<Mrows, 256>>>(qcur, qbuf, X16, ATT, gA + i,
                                       ln1g + (size_t)i * Dm, ln1b + (size_t)i * Dm);

        gemm_h<1,1><<<gF1g, 128, GEMM_SMEM>>>(X16, WT1, bf1 + i * DFFv, F1h, Mrows, DFFv, Dm);
        gemm_h<0,0><<<gP, 128, GEMM_SMEM>>>(F1h, WT2, bf2 + i * Dm, ATT, Mrows, Dm, DFFv);
        addnorm_kernel<<<Mrows, 256>>>(qbuf, qbuf, X16, ATT, gF + i,
                                       ln2g + (size_t)i * Dm, ln2b + (size_t)i * Dm);
    }
}